// round 12
// baseline (speedup 1.0000x reference)
#include <cuda_runtime.h>
#include <cstdint>

// Problem constants (B=4, S=1024, K=32, V=32000)
#define BB 4
#define SS 1024
#define KK 32
#define VV 32000
#define ROWS (BB * SS)          // 4096
#define CHUNK 1024              // floats per block (256 threads * float4)
#define NCHUNK ((VV + CHUNK - 1) / CHUNK)   // 32 (last chunk = 256 floats)
#define WWIN 128                // floats per warp window (32 threads * 4)

// Scratch (device globals — no allocation). Deduped per-row scatter list.
__device__ float g_probs[ROWS * KK];
__device__ int   g_tgt  [ROWS * KK];

__device__ __forceinline__ float fast_tanh(float x) {
    float r;
    asm("tanh.approx.f32 %0, %1;" : "=f"(r) : "f"(x));
    return r;
}

// ---------------------------------------------------------------------------
// Kernel A (proven ~4.7us): one warp per row, 8 rows/block (512 blocks).
// Fast chain: label counts via match_any+ballot+popc; fc2 feats staged in
// smem; in-warp duplicate-target combine so kernel B can use plain stores.
// Dropped duplicate lanes publish t = -1.
// ---------------------------------------------------------------------------
__global__ void __launch_bounds__(256) compute_kernel(
    const int*   __restrict__ tgt,
    const float* __restrict__ dists,
    const float* __restrict__ kkf,
    const float* __restrict__ nsp,
    const float* __restrict__ fc1_w1,  // (2,4)
    const float* __restrict__ fc1_b1,  // (4)
    const float* __restrict__ fc1_w2,  // (4,1)
    const float* __restrict__ fc1_b2,  // (1)
    const float* __restrict__ fc2_w1,  // (64,32)
    const float* __restrict__ fc2_b1,  // (32)
    const float* __restrict__ fc2_w2,  // (32,2)
    const float* __restrict__ fc2_b2)  // (2)
{
    const unsigned FULL = 0xffffffffu;
    __shared__ float feat[8][64];
    __shared__ float sp  [8][32];

    const int w    = threadIdx.x >> 5;
    const int lane = threadIdx.x & 31;
    const int row  = blockIdx.x * 8 + w;
    const int base = row * KK + lane;

    int   t   = tgt[base];
    float d   = dists[base];
    float lkf = __logf(kkf[base]);
    float lsp = __logf(nsp[base]);

    // label_counts: distinct nonzero labels in prefix [0..lane]
    unsigned mgrp = __match_any_sync(FULL, t);
    int leader = __ffs(mgrp) - 1;
    bool fo = (t != 0) && (leader == lane);
    unsigned fomask = __ballot_sync(FULL, fo);
    float lc = (float)__popc(fomask & (0xFFFFFFFFu >> (31 - lane)));

    // fc1 -> noise_logit
    float noise = fc1_b2[0];
    #pragma unroll
    for (int m = 0; m < 4; m++) {
        float h = fmaf(lkf, fc1_w1[m], fmaf(lsp, fc1_w1[4 + m], fc1_b1[m]));
        noise = fmaf(fast_tanh(h), fc1_w2[m], noise);
    }

    // stage feats, then fc2: hidden[lane] = b1 + sum_j feat[j]*W1[j][lane]
    feat[w][lane]      = d;
    feat[w][32 + lane] = lc;
    __syncwarp();
    float hid = fc2_b1[lane];
    #pragma unroll
    for (int j = 0; j < 64; j++) {
        hid = fmaf(feat[w][j], fc2_w1[j * 32 + lane], hid);
    }
    float ht = fast_tanh(hid);

    // lambda_logit[1] -> tempe
    float l1 = ht * fc2_w2[lane * 2 + 1];
    #pragma unroll
    for (int off = 16; off; off >>= 1) l1 += __shfl_xor_sync(FULL, l1, off);
    l1 += fc2_b2[1];
    float tempe = 1.f / (1.f + __expf(-l1));

    // softmax over K of (-d*tempe + noise)
    float logit = fmaf(-d, tempe, noise);
    float mx = logit;
    #pragma unroll
    for (int off = 16; off; off >>= 1) mx = fmaxf(mx, __shfl_xor_sync(FULL, mx, off));
    float e = __expf(logit - mx);
    float s = e;
    #pragma unroll
    for (int off = 16; off; off >>= 1) s += __shfl_xor_sync(FULL, s, off);
    float p = e / s;

    // in-warp duplicate-target combine (group-sum via smem)
    sp[w][lane] = p;
    __syncwarp();
    float psum = p;
    unsigned m = mgrp & ~(1u << lane);
    while (m) { int j = __ffs(m) - 1; psum += sp[w][j]; m &= m - 1; }

    g_tgt  [base] = (leader == lane) ? t : -1;
    g_probs[base] = psum;
}

// ---------------------------------------------------------------------------
// Kernel B: zero + inline scatter, per-warp ownership (NO block barrier).
// One block per 1024-float chunk of one row. Each warp zeroes its own
// 128-float window (1 float4/thread), __syncwarp (intra-warp memory fence),
// then all 32 lanes check the row's deduped targets against THIS warp's
// window and plain-store hits. Zero->scatter ordering is intra-warp only.
// ---------------------------------------------------------------------------
__global__ void __launch_bounds__(256) zero_scatter_kernel(
    float* __restrict__ out)
{
    const int row   = blockIdx.y;
    const int chunk = blockIdx.x;
    const int tid   = threadIdx.x;
    const int w     = tid >> 5;
    const int lane  = tid & 31;

    const int lo  = chunk * CHUNK;           // chunk base within row
    const int n   = min(CHUNK, VV - lo);     // 1024, or 256 for last chunk
    const int wlo = w * WWIN;                // warp window base within chunk
    float* rowp = out + (size_t)row * VV + lo;

    // zero this warp's window: one float4 per thread
    int i4 = wlo + lane * 4;
    if (i4 < n) *(float4*)(rowp + i4) = make_float4(0.f, 0.f, 0.f, 0.f);

    __syncwarp();  // intra-warp: order zero stores before scatter stores

    // scatter: each warp handles targets in its own window
    int   t = g_tgt  [row * KK + lane];      // -1 for dropped duplicates
    int loc = t - lo - wlo;
    if (loc >= 0 && loc < WWIN && (wlo + loc) < n) {
        float p = g_probs[row * KK + lane];
        rowp[wlo + loc] = p;
    }
}

// metadata order:
//  0 tgt_index(i32) 1 knn_dists 2 knn_key_feature 3 network_probs(UNUSED)
//  4 network_select_probs 5 dfc_w(UNUSED) 6 dfc_b(UNUSED)
//  7 fc1_w1 8 fc1_b1 9 fc1_w2 10 fc1_b2 11 fc2_w1 12 fc2_b1 13 fc2_w2 14 fc2_b2
extern "C" void kernel_launch(void* const* d_in, const int* in_sizes, int n_in,
                              void* d_out, int out_size) {
    const int*   tgt    = (const int*)  d_in[0];
    const float* dists  = (const float*)d_in[1];
    const float* kkf    = (const float*)d_in[2];
    const float* nsp    = (const float*)d_in[4];
    const float* fc1_w1 = (const float*)d_in[7];
    const float* fc1_b1 = (const float*)d_in[8];
    const float* fc1_w2 = (const float*)d_in[9];
    const float* fc1_b2 = (const float*)d_in[10];
    const float* fc2_w1 = (const float*)d_in[11];
    const float* fc2_b1 = (const float*)d_in[12];
    const float* fc2_w2 = (const float*)d_in[13];
    const float* fc2_b2 = (const float*)d_in[14];
    float* out = (float*)d_out;

    // A: 4096 rows, 8 rows/block -> 512 blocks (one wave)
    compute_kernel<<<ROWS / 8, 256>>>(tgt, dists, kkf, nsp,
                                      fc1_w1, fc1_b1, fc1_w2, fc1_b2,
                                      fc2_w1, fc2_b1, fc2_w2, fc2_b2);

    // B: flat zero+scatter, grid (32 chunks, 4096 rows)
    dim3 grid(NCHUNK, ROWS);
    zero_scatter_kernel<<<grid, 256>>>(out);
}

// round 13
// speedup vs baseline: 1.4232x; 1.4232x over previous
#include <cuda_runtime.h>
#include <cstdint>

// Problem constants (B=4, S=1024, K=32, V=32000)
#define BB 4
#define SS 1024
#define KK 32
#define VV 32000
#define ROWS (BB * SS)          // 4096
#define CHUNK 1024              // floats per zero-block (256 threads * float4)
#define NCHUNK ((VV + CHUNK - 1) / CHUNK)   // 32 (last chunk = 256 floats)

// Scratch (device global — no allocation). Packed deduped scatter list:
// .x = target index (or -1 for dropped duplicate lanes), .y = float bits of p.
__device__ int2 g_scat[ROWS * KK];

__device__ __forceinline__ float fast_tanh(float x) {
    float r;
    asm("tanh.approx.f32 %0, %1;" : "=f"(r) : "f"(x));
    return r;
}

// ---------------------------------------------------------------------------
// Kernel A (~4.7us): one warp per row, 8 rows/block (512 blocks, one wave).
// Fast chain: label counts via match_any+ballot+popc; fc2 feats staged in
// smem; in-warp duplicate-target combine so kernel B can use plain stores.
// ---------------------------------------------------------------------------
__global__ void __launch_bounds__(256) compute_kernel(
    const int*   __restrict__ tgt,
    const float* __restrict__ dists,
    const float* __restrict__ kkf,
    const float* __restrict__ nsp,
    const float* __restrict__ fc1_w1,  // (2,4)
    const float* __restrict__ fc1_b1,  // (4)
    const float* __restrict__ fc1_w2,  // (4,1)
    const float* __restrict__ fc1_b2,  // (1)
    const float* __restrict__ fc2_w1,  // (64,32)
    const float* __restrict__ fc2_b1,  // (32)
    const float* __restrict__ fc2_w2,  // (32,2)
    const float* __restrict__ fc2_b2)  // (2)
{
    const unsigned FULL = 0xffffffffu;
    __shared__ float feat[8][64];
    __shared__ float sp  [8][32];

    const int w    = threadIdx.x >> 5;
    const int lane = threadIdx.x & 31;
    const int row  = blockIdx.x * 8 + w;
    const int base = row * KK + lane;

    int   t   = tgt[base];
    float d   = dists[base];
    float lkf = __logf(kkf[base]);
    float lsp = __logf(nsp[base]);

    // label_counts: distinct nonzero labels in prefix [0..lane]
    unsigned mgrp = __match_any_sync(FULL, t);
    int leader = __ffs(mgrp) - 1;
    bool fo = (t != 0) && (leader == lane);
    unsigned fomask = __ballot_sync(FULL, fo);
    float lc = (float)__popc(fomask & (0xFFFFFFFFu >> (31 - lane)));

    // fc1 -> noise_logit
    float noise = fc1_b2[0];
    #pragma unroll
    for (int m = 0; m < 4; m++) {
        float h = fmaf(lkf, fc1_w1[m], fmaf(lsp, fc1_w1[4 + m], fc1_b1[m]));
        noise = fmaf(fast_tanh(h), fc1_w2[m], noise);
    }

    // stage feats, then fc2: hidden[lane] = b1 + sum_j feat[j]*W1[j][lane]
    feat[w][lane]      = d;
    feat[w][32 + lane] = lc;
    __syncwarp();
    float hid = fc2_b1[lane];
    #pragma unroll
    for (int j = 0; j < 64; j++) {
        hid = fmaf(feat[w][j], fc2_w1[j * 32 + lane], hid);
    }
    float ht = fast_tanh(hid);

    // lambda_logit[1] -> tempe
    float l1 = ht * fc2_w2[lane * 2 + 1];
    #pragma unroll
    for (int off = 16; off; off >>= 1) l1 += __shfl_xor_sync(FULL, l1, off);
    l1 += fc2_b2[1];
    float tempe = 1.f / (1.f + __expf(-l1));

    // softmax over K of (-d*tempe + noise)
    float logit = fmaf(-d, tempe, noise);
    float mx = logit;
    #pragma unroll
    for (int off = 16; off; off >>= 1) mx = fmaxf(mx, __shfl_xor_sync(FULL, mx, off));
    float e = __expf(logit - mx);
    float s = e;
    #pragma unroll
    for (int off = 16; off; off >>= 1) s += __shfl_xor_sync(FULL, s, off);
    float p = e / s;

    // in-warp duplicate-target combine (group-sum via smem)
    sp[w][lane] = p;
    __syncwarp();
    float psum = p;
    unsigned m = mgrp & ~(1u << lane);
    while (m) { int j = __ffs(m) - 1; psum += sp[w][j]; m &= m - 1; }

    g_scat[base] = make_int2((leader == lane) ? t : -1, __float_as_int(psum));
}

// ---------------------------------------------------------------------------
// Kernel B: zero + inline scatter — R4/R8 proven shape.
// One block per 1024-float chunk of one row; 1 float4 store per thread.
// Warp 0 prefetches the packed scatter list (one LDG.64 per lane), then
// after the block barrier plain-stores any target landing in this chunk.
// ---------------------------------------------------------------------------
__global__ void __launch_bounds__(256) zero_scatter_kernel(
    float* __restrict__ out)
{
    const int row   = blockIdx.y;
    const int chunk = blockIdx.x;
    const int tid   = threadIdx.x;

    const int lo = chunk * CHUNK;
    const int n  = min(CHUNK, VV - lo);          // 1024, or 256 for last chunk
    float* rowp = out + (size_t)row * VV + lo;

    // prefetch the packed scatter entry (warp 0) before the stores
    int2 sc = make_int2(-1, 0);
    if (tid < 32) sc = g_scat[row * KK + tid];

    // zero this chunk: one float4 per thread
    int i4 = tid * 4;
    if (i4 < n) *(float4*)(rowp + i4) = make_float4(0.f, 0.f, 0.f, 0.f);

    __syncthreads();  // order zero-stores before the targeted stores

    if (tid < 32) {
        int loc = sc.x - lo;
        if (loc >= 0 && loc < n) rowp[loc] = __int_as_float(sc.y);
    }
}

// metadata order:
//  0 tgt_index(i32) 1 knn_dists 2 knn_key_feature 3 network_probs(UNUSED)
//  4 network_select_probs 5 dfc_w(UNUSED) 6 dfc_b(UNUSED)
//  7 fc1_w1 8 fc1_b1 9 fc1_w2 10 fc1_b2 11 fc2_w1 12 fc2_b1 13 fc2_w2 14 fc2_b2
extern "C" void kernel_launch(void* const* d_in, const int* in_sizes, int n_in,
                              void* d_out, int out_size) {
    const int*   tgt    = (const int*)  d_in[0];
    const float* dists  = (const float*)d_in[1];
    const float* kkf    = (const float*)d_in[2];
    const float* nsp    = (const float*)d_in[4];
    const float* fc1_w1 = (const float*)d_in[7];
    const float* fc1_b1 = (const float*)d_in[8];
    const float* fc1_w2 = (const float*)d_in[9];
    const float* fc1_b2 = (const float*)d_in[10];
    const float* fc2_w1 = (const float*)d_in[11];
    const float* fc2_b1 = (const float*)d_in[12];
    const float* fc2_w2 = (const float*)d_in[13];
    const float* fc2_b2 = (const float*)d_in[14];
    float* out = (float*)d_out;

    // A: 4096 rows, 8 rows/block -> 512 blocks (one wave)
    compute_kernel<<<ROWS / 8, 256>>>(tgt, dists, kkf, nsp,
                                      fc1_w1, fc1_b1, fc1_w2, fc1_b2,
                                      fc2_w1, fc2_b1, fc2_w2, fc2_b2);

    // B: flat zero+scatter, grid (32 chunks, 4096 rows)
    dim3 grid(NCHUNK, ROWS);
    zero_scatter_kernel<<<grid, 256>>>(out);
}

// round 14
// speedup vs baseline: 1.4414x; 1.0128x over previous
#include <cuda_runtime.h>
#include <cstdint>

// Problem constants (B=4, S=1024, K=32, V=32000)
#define BB 4
#define SS 1024
#define KK 32
#define VV 32000
#define ROWS (BB * SS)          // 4096
#define CHUNK 2048              // floats per block (256 threads * 2 * float4)
#define NCHUNK ((VV + CHUNK - 1) / CHUNK)   // 16 (last chunk = 1280 floats)

// Scratch (device global — no allocation). Packed deduped scatter list:
// .x = target index (or -1 for dropped duplicate lanes), .y = float bits of p.
__device__ int2 g_scat[ROWS * KK];

__device__ __forceinline__ float fast_tanh(float x) {
    float r;
    asm("tanh.approx.f32 %0, %1;" : "=f"(r) : "f"(x));
    return r;
}

// ---------------------------------------------------------------------------
// Kernel A (~4.2us): one warp per row, 8 rows/block (512 blocks, one wave).
// Fast chain: label counts via match_any+ballot+popc; fc2 feats staged in
// smem; in-warp duplicate-target combine so kernel B can use plain stores.
// ---------------------------------------------------------------------------
__global__ void __launch_bounds__(256) compute_kernel(
    const int*   __restrict__ tgt,
    const float* __restrict__ dists,
    const float* __restrict__ kkf,
    const float* __restrict__ nsp,
    const float* __restrict__ fc1_w1,  // (2,4)
    const float* __restrict__ fc1_b1,  // (4)
    const float* __restrict__ fc1_w2,  // (4,1)
    const float* __restrict__ fc1_b2,  // (1)
    const float* __restrict__ fc2_w1,  // (64,32)
    const float* __restrict__ fc2_b1,  // (32)
    const float* __restrict__ fc2_w2,  // (32,2)
    const float* __restrict__ fc2_b2)  // (2)
{
    const unsigned FULL = 0xffffffffu;
    __shared__ float feat[8][64];
    __shared__ float sp  [8][32];

    const int w    = threadIdx.x >> 5;
    const int lane = threadIdx.x & 31;
    const int row  = blockIdx.x * 8 + w;
    const int base = row * KK + lane;

    int   t   = tgt[base];
    float d   = dists[base];
    float lkf = __logf(kkf[base]);
    float lsp = __logf(nsp[base]);

    // label_counts: distinct nonzero labels in prefix [0..lane]
    unsigned mgrp = __match_any_sync(FULL, t);
    int leader = __ffs(mgrp) - 1;
    bool fo = (t != 0) && (leader == lane);
    unsigned fomask = __ballot_sync(FULL, fo);
    float lc = (float)__popc(fomask & (0xFFFFFFFFu >> (31 - lane)));

    // fc1 -> noise_logit
    float noise = fc1_b2[0];
    #pragma unroll
    for (int m = 0; m < 4; m++) {
        float h = fmaf(lkf, fc1_w1[m], fmaf(lsp, fc1_w1[4 + m], fc1_b1[m]));
        noise = fmaf(fast_tanh(h), fc1_w2[m], noise);
    }

    // stage feats, then fc2: hidden[lane] = b1 + sum_j feat[j]*W1[j][lane]
    feat[w][lane]      = d;
    feat[w][32 + lane] = lc;
    __syncwarp();
    float hid = fc2_b1[lane];
    #pragma unroll
    for (int j = 0; j < 64; j++) {
        hid = fmaf(feat[w][j], fc2_w1[j * 32 + lane], hid);
    }
    float ht = fast_tanh(hid);

    // lambda_logit[1] -> tempe
    float l1 = ht * fc2_w2[lane * 2 + 1];
    #pragma unroll
    for (int off = 16; off; off >>= 1) l1 += __shfl_xor_sync(FULL, l1, off);
    l1 += fc2_b2[1];
    float tempe = 1.f / (1.f + __expf(-l1));

    // softmax over K of (-d*tempe + noise)
    float logit = fmaf(-d, tempe, noise);
    float mx = logit;
    #pragma unroll
    for (int off = 16; off; off >>= 1) mx = fmaxf(mx, __shfl_xor_sync(FULL, mx, off));
    float e = __expf(logit - mx);
    float s = e;
    #pragma unroll
    for (int off = 16; off; off >>= 1) s += __shfl_xor_sync(FULL, s, off);
    float p = e / s;

    // in-warp duplicate-target combine (group-sum via smem)
    sp[w][lane] = p;
    __syncwarp();
    float psum = p;
    unsigned m = mgrp & ~(1u << lane);
    while (m) { int j = __ffs(m) - 1; psum += sp[w][j]; m &= m - 1; }

    g_scat[base] = make_int2((leader == lane) ? t : -1, __float_as_int(psum));
}

// ---------------------------------------------------------------------------
// Kernel B: zero + inline scatter. Same shape as R13 but each thread issues
// TWO independent float4 stores (CHUNK=2048), halving the number of blocks
// and thus all per-block overheads (launch, prefetch LDG, barrier).
// ---------------------------------------------------------------------------
__global__ void __launch_bounds__(256) zero_scatter_kernel(
    float* __restrict__ out)
{
    const int row   = blockIdx.y;
    const int chunk = blockIdx.x;
    const int tid   = threadIdx.x;

    const int lo = chunk * CHUNK;
    const int n  = min(CHUNK, VV - lo);         // 2048, or 1280 for last chunk
    float* rowp = out + (size_t)row * VV + lo;

    // prefetch the packed scatter entry (warp 0) before the stores
    int2 sc = make_int2(-1, 0);
    if (tid < 32) sc = g_scat[row * KK + tid];

    // zero this chunk: two independent float4 stores per thread
    const float4 z = make_float4(0.f, 0.f, 0.f, 0.f);
    int i4 = tid * 4;
    if (i4 < n)        *(float4*)(rowp + i4)        = z;
    if (i4 + 1024 < n) *(float4*)(rowp + i4 + 1024) = z;

    __syncthreads();  // order zero-stores before the targeted stores

    if (tid < 32) {
        int loc = sc.x - lo;
        if (loc >= 0 && loc < n) rowp[loc] = __int_as_float(sc.y);
    }
}

// metadata order:
//  0 tgt_index(i32) 1 knn_dists 2 knn_key_feature 3 network_probs(UNUSED)
//  4 network_select_probs 5 dfc_w(UNUSED) 6 dfc_b(UNUSED)
//  7 fc1_w1 8 fc1_b1 9 fc1_w2 10 fc1_b2 11 fc2_w1 12 fc2_b1 13 fc2_w2 14 fc2_b2
extern "C" void kernel_launch(void* const* d_in, const int* in_sizes, int n_in,
                              void* d_out, int out_size) {
    const int*   tgt    = (const int*)  d_in[0];
    const float* dists  = (const float*)d_in[1];
    const float* kkf    = (const float*)d_in[2];
    const float* nsp    = (const float*)d_in[4];
    const float* fc1_w1 = (const float*)d_in[7];
    const float* fc1_b1 = (const float*)d_in[8];
    const float* fc1_w2 = (const float*)d_in[9];
    const float* fc1_b2 = (const float*)d_in[10];
    const float* fc2_w1 = (const float*)d_in[11];
    const float* fc2_b1 = (const float*)d_in[12];
    const float* fc2_w2 = (const float*)d_in[13];
    const float* fc2_b2 = (const float*)d_in[14];
    float* out = (float*)d_out;

    // A: 4096 rows, 8 rows/block -> 512 blocks (one wave)
    compute_kernel<<<ROWS / 8, 256>>>(tgt, dists, kkf, nsp,
                                      fc1_w1, fc1_b1, fc1_w2, fc1_b2,
                                      fc2_w1, fc2_b1, fc2_w2, fc2_b2);

    // B: flat zero+scatter, grid (16 chunks, 4096 rows)
    dim3 grid(NCHUNK, ROWS);
    zero_scatter_kernel<<<grid, 256>>>(out);
}